// round 1
// baseline (speedup 1.0000x reference)
#include <cuda_runtime.h>
#include <math.h>

// ---------------------------------------------------------------------------
// Problem constants (shapes are fixed by the reference):
//   x: (B=2, D=8, H=56, W=56, C=384)  window (2,7,7)  shift (1,3,3)  heads=12
//   T = 2*8*56*56 = 50176 tokens, N_win = 98, windows B_ = 512, nW = 256
// ---------------------------------------------------------------------------
#define T_TOK   50176
#define C_DIM   384
#define HEADS   12
#define HD      32
#define NWIN    98          // tokens per window
#define BWIN    512         // total windows
#define HID     1536        // MLP hidden

// Scratch (device globals: allocation-free rule)
__device__ float g_xw [T_TOK * C_DIM];        // LN1 + shift + window-partitioned
__device__ float g_qkv[T_TOK * 3 * C_DIM];    // qkv projection (token-major, [3,h,hd])
__device__ float g_att[T_TOK * C_DIM];        // attention output (windowed order)
__device__ float g_x1 [T_TOK * C_DIM];        // x + attn branch (original order)
__device__ float g_ln2[T_TOK * C_DIM];        // LN2(x1)
__device__ float g_fc1[T_TOK * HID];          // gelu(fc1)

// Map windowed-token row r -> original-layout token index.
// Windowed r = b_*98 + n; b_ = ((b*4+dI)*8+hI)*8+wI; n = dd*49+hh*7+ww.
// Shifted coords (ds,hs,ws) = (dI*2+dd, hI*7+hh, wI*7+ww); original coords are
// shifted rolled back by (+1,+3,+3).
__device__ __forceinline__ int remap_row(int r) {
    int b_ = r / NWIN, n = r - b_ * NWIN;
    int b    = b_ >> 8;
    int widx = b_ & 255;
    int dI = widx >> 6, hI = (widx >> 3) & 7, wI = widx & 7;
    int dd = n / 49, rem = n - dd * 49, hh = rem / 7, ww = rem - hh * 7;
    int ds = dI * 2 + dd, hs = hI * 7 + hh, ws = wI * 7 + ww;
    int d = (ds + 1) & 7;
    int h = hs + 3; if (h >= 56) h -= 56;
    int w = ws + 3; if (w >= 56) w -= 56;
    return ((b * 8 + d) * 56 + h) * 56 + w;
}

// ---------------------------------------------------------------------------
// LayerNorm over C=384. One block per token, 128 threads (3 channels each).
// REMAP=true: output row r (windowed order) sources from original token
// remap_row(r)  -> fuses LN1 + roll + window_partition in one pass.
// ---------------------------------------------------------------------------
template<bool REMAP>
__global__ void ln_kernel(const float* __restrict__ in,
                          const float* __restrict__ gw,
                          const float* __restrict__ gb,
                          float* __restrict__ out) {
    int r   = blockIdx.x;
    int tid = threadIdx.x;
    int src = REMAP ? remap_row(r) : r;
    const float* px = in + (size_t)src * C_DIM;

    float v[3];
    float sum = 0.f, sq = 0.f;
#pragma unroll
    for (int i = 0; i < 3; ++i) {
        float t = px[tid + i * 128];
        v[i] = t; sum += t; sq += t * t;
    }
#pragma unroll
    for (int o = 16; o > 0; o >>= 1) {
        sum += __shfl_xor_sync(0xffffffffu, sum, o);
        sq  += __shfl_xor_sync(0xffffffffu, sq,  o);
    }
    __shared__ float red[8];
    int warp = tid >> 5;
    if ((tid & 31) == 0) { red[warp] = sum; red[4 + warp] = sq; }
    __syncthreads();
    float ts = red[0] + red[1] + red[2] + red[3];
    float tq = red[4] + red[5] + red[6] + red[7];
    float mean = ts * (1.0f / C_DIM);
    float var  = tq * (1.0f / C_DIM) - mean * mean;
    float rstd = rsqrtf(var + 1e-5f);

    float* po = out + (size_t)r * C_DIM;
#pragma unroll
    for (int i = 0; i < 3; ++i) {
        int c = tid + i * 128;
        po[c] = (v[i] - mean) * rstd * gw[c] + gb[c];
    }
}

// ---------------------------------------------------------------------------
// SGEMM: C[M,N] = A[M,K] @ B[N,K]^T (+bias, epilogue variants)
// BM=BN=128, BK=16, 256 threads, 8x8 register tiles, float4 global loads.
// All dims are exact multiples -> no bounds checks.
// EPI: 0 = +bias
//      1 = +bias, exact GELU
//      2 = +bias, += res[row]        (fc2 + residual, writes d_out)
//      3 = +bias, row -> remap_row(row), += res[orig]  (proj + shortcut)
// ---------------------------------------------------------------------------
template<int EPI>
__global__ __launch_bounds__(256, 2)
void gemm_nt(const float* __restrict__ A, const float* __restrict__ B,
             const float* __restrict__ bias, float* __restrict__ Cmat,
             int M, int N, int K, const float* __restrict__ res) {
    __shared__ float As[16][128];
    __shared__ float Bs[16][128];

    int tid = threadIdx.x;
    int tx = tid & 15, ty = tid >> 4;
    int m0 = blockIdx.y * 128, n0 = blockIdx.x * 128;

    float acc[8][8];
#pragma unroll
    for (int i = 0; i < 8; ++i)
#pragma unroll
        for (int j = 0; j < 8; ++j) acc[i][j] = 0.f;

    for (int k0 = 0; k0 < K; k0 += 16) {
#pragma unroll
        for (int l = 0; l < 2; ++l) {
            int f   = tid + l * 256;       // float4 index in [0,512)
            int row = f >> 2;
            int kc  = (f & 3) * 4;
            float4 va = *(const float4*)&A[(size_t)(m0 + row) * K + k0 + kc];
            As[kc + 0][row] = va.x; As[kc + 1][row] = va.y;
            As[kc + 2][row] = va.z; As[kc + 3][row] = va.w;
            float4 vb = *(const float4*)&B[(size_t)(n0 + row) * K + k0 + kc];
            Bs[kc + 0][row] = vb.x; Bs[kc + 1][row] = vb.y;
            Bs[kc + 2][row] = vb.z; Bs[kc + 3][row] = vb.w;
        }
        __syncthreads();
#pragma unroll
        for (int k = 0; k < 16; ++k) {
            float4 a0 = *(const float4*)&As[k][ty * 8];
            float4 a1 = *(const float4*)&As[k][ty * 8 + 4];
            float4 b0 = *(const float4*)&Bs[k][tx * 8];
            float4 b1 = *(const float4*)&Bs[k][tx * 8 + 4];
            float a[8] = {a0.x, a0.y, a0.z, a0.w, a1.x, a1.y, a1.z, a1.w};
            float b[8] = {b0.x, b0.y, b0.z, b0.w, b1.x, b1.y, b1.z, b1.w};
#pragma unroll
            for (int i = 0; i < 8; ++i)
#pragma unroll
                for (int j = 0; j < 8; ++j) acc[i][j] += a[i] * b[j];
        }
        __syncthreads();
    }

    int colb = n0 + tx * 8;
#pragma unroll
    for (int i = 0; i < 8; ++i) {
        int r = m0 + ty * 8 + i;
        size_t rowoff;
        if (EPI == 3) rowoff = (size_t)remap_row(r) * N;
        else          rowoff = (size_t)r * N;
#pragma unroll
        for (int j = 0; j < 8; ++j) {
            int c = colb + j;
            float v = acc[i][j] + bias[c];
            if (EPI == 1) v = 0.5f * v * (1.0f + erff(v * 0.70710678118654752f));
            if (EPI == 2 || EPI == 3) v += res[rowoff + c];
            Cmat[rowoff + c] = v;
        }
    }
}

// ---------------------------------------------------------------------------
// Attention: one block per (window b_, head). 128 threads.
// Dynamic smem: q,k,v (98x32 each) + scores (98x99) = 76440 B.
// Relative-position bias and shift mask computed analytically in-register.
// ---------------------------------------------------------------------------
__global__ void attn_kernel(const float* __restrict__ qkv,
                            const float* __restrict__ rpb,
                            float* __restrict__ out) {
    extern __shared__ float sm[];
    float* qs = sm;                   // 98*32
    float* ks = qs + NWIN * HD;       // 98*32
    float* vs = ks + NWIN * HD;       // 98*32
    float* sc = vs + NWIN * HD;       // 98*99 (padded rows)

    int b_   = blockIdx.x;
    int head = blockIdx.y;
    int tid  = threadIdx.x;
    const float scale = 0.17677669529663687f;   // 32^-0.5

    size_t base = (size_t)b_ * NWIN * (3 * C_DIM);
    for (int idx = tid; idx < NWIN * HD; idx += 128) {
        int m = idx >> 5, d = idx & 31;
        size_t o = base + (size_t)m * (3 * C_DIM) + head * HD + d;
        qs[idx] = qkv[o] * scale;
        ks[idx] = qkv[o + C_DIM];
        vs[idx] = qkv[o + 2 * C_DIM];
    }
    __syncthreads();

    int widx = b_ & 255;
    int dI = widx >> 6, hI = (widx >> 3) & 7, wI = widx & 7;

    for (int idx = tid; idx < NWIN * NWIN; idx += 128) {
        int n = idx / NWIN, m = idx - n * NWIN;
        float s = 0.f;
#pragma unroll
        for (int d = 0; d < HD; ++d) s += qs[n * HD + d] * ks[m * HD + d];
        // window-local coords
        int nd = n / 49, nr = n - nd * 49, nh = nr / 7, nw = nr - nh * 7;
        int md = m / 49, mr = m - md * 49, mh = mr / 7, mw = mr - mh * 7;
        // relative position bias: table shape (3*13*13, 12)
        int ridx = (nd - md + 1) * 169 + (nh - mh + 6) * 13 + (nw - mw + 6);
        s += rpb[ridx * HEADS + head];
        // shift mask: region labels in shifted-frame global coords
        int gdn = dI * 2 + nd, ghn = hI * 7 + nh, gwn = wI * 7 + nw;
        int gdm = dI * 2 + md, ghm = hI * 7 + mh, gwm = wI * 7 + mw;
        int ln = (gdn < 6 ? 0 : (gdn < 7 ? 1 : 2)) * 9
               + (ghn < 49 ? 0 : (ghn < 53 ? 1 : 2)) * 3
               + (gwn < 49 ? 0 : (gwn < 53 ? 1 : 2));
        int lm = (gdm < 6 ? 0 : (gdm < 7 ? 1 : 2)) * 9
               + (ghm < 49 ? 0 : (ghm < 53 ? 1 : 2)) * 3
               + (gwm < 49 ? 0 : (gwm < 53 ? 1 : 2));
        if (ln != lm) s -= 100.0f;
        sc[n * 99 + m] = s;
    }
    __syncthreads();

    // softmax, one thread per row
    if (tid < NWIN) {
        float mx = -1e30f;
        for (int m = 0; m < NWIN; ++m) mx = fmaxf(mx, sc[tid * 99 + m]);
        float sum = 0.f;
        for (int m = 0; m < NWIN; ++m) {
            float e = __expf(sc[tid * 99 + m] - mx);
            sc[tid * 99 + m] = e; sum += e;
        }
        float inv = 1.0f / sum;
        for (int m = 0; m < NWIN; ++m) sc[tid * 99 + m] *= inv;
    }
    __syncthreads();

    for (int idx = tid; idx < NWIN * HD; idx += 128) {
        int n = idx >> 5, d = idx & 31;
        float s = 0.f;
        for (int m = 0; m < NWIN; ++m) s += sc[n * 99 + m] * vs[m * HD + d];
        out[((size_t)b_ * NWIN + n) * C_DIM + head * HD + d] = s;
    }
}

// ---------------------------------------------------------------------------
// Launch sequence
// ---------------------------------------------------------------------------
extern "C" void kernel_launch(void* const* d_in, const int* in_sizes, int n_in,
                              void* d_out, int out_size) {
    const float* x     = (const float*)d_in[0];
    const float* n1w   = (const float*)d_in[1];
    const float* n1b   = (const float*)d_in[2];
    const float* qkvw  = (const float*)d_in[3];
    const float* qkvb  = (const float*)d_in[4];
    const float* rpb   = (const float*)d_in[5];
    const float* projw = (const float*)d_in[6];
    const float* projb = (const float*)d_in[7];
    const float* n2w   = (const float*)d_in[8];
    const float* n2b   = (const float*)d_in[9];
    const float* fc1w  = (const float*)d_in[10];
    const float* fc1b  = (const float*)d_in[11];
    const float* fc2w  = (const float*)d_in[12];
    const float* fc2b  = (const float*)d_in[13];
    float* out = (float*)d_out;

    float *xw, *qkv, *att, *x1, *ln2, *fc1;
    cudaGetSymbolAddress((void**)&xw,  g_xw);
    cudaGetSymbolAddress((void**)&qkv, g_qkv);
    cudaGetSymbolAddress((void**)&att, g_att);
    cudaGetSymbolAddress((void**)&x1,  g_x1);
    cudaGetSymbolAddress((void**)&ln2, g_ln2);
    cudaGetSymbolAddress((void**)&fc1, g_fc1);

    const int ATTN_SMEM = (3 * NWIN * HD + NWIN * 99) * (int)sizeof(float); // 76440
    cudaFuncSetAttribute(attn_kernel, cudaFuncAttributeMaxDynamicSharedMemorySize, ATTN_SMEM);

    // 1. LN1 + shift + window partition
    ln_kernel<true><<<T_TOK, 128>>>(x, n1w, n1b, xw);

    // 2. QKV projection: (T,384) @ (1152,384)^T
    gemm_nt<0><<<dim3(1152 / 128, T_TOK / 128), 256>>>(xw, qkvw, qkvb, qkv,
                                                       T_TOK, 3 * C_DIM, C_DIM, nullptr);

    // 3. Windowed attention
    attn_kernel<<<dim3(BWIN, HEADS), 128, ATTN_SMEM>>>(qkv, rpb, att);

    // 4. Proj + window reverse + roll back + shortcut  -> x1 (original order)
    gemm_nt<3><<<dim3(C_DIM / 128, T_TOK / 128), 256>>>(att, projw, projb, x1,
                                                        T_TOK, C_DIM, C_DIM, x);

    // 5. LN2
    ln_kernel<false><<<T_TOK, 128>>>(x1, n2w, n2b, ln2);

    // 6. FC1 + exact GELU
    gemm_nt<1><<<dim3(HID / 128, T_TOK / 128), 256>>>(ln2, fc1w, fc1b, fc1,
                                                      T_TOK, HID, C_DIM, nullptr);

    // 7. FC2 + residual -> d_out
    gemm_nt<2><<<dim3(C_DIM / 128, T_TOK / 128), 256>>>(fc1, fc2w, fc2b, out,
                                                        T_TOK, C_DIM, HID, x1);
}

// round 2
// speedup vs baseline: 1.9949x; 1.9949x over previous
#include <cuda_runtime.h>
#include <math.h>
#include <mma.h>

using namespace nvcuda;
using tf32_t = wmma::precision::tf32;

#define T_TOK   50176
#define C_DIM   384
#define HEADS   12
#define HD      32
#define NWIN    98
#define BWIN    512
#define HID     1536

// Scratch (device globals: allocation-free rule)
__device__ float g_xw [T_TOK * C_DIM];
__device__ float g_qkv[T_TOK * 3 * C_DIM];
__device__ float g_att[T_TOK * C_DIM];
__device__ float g_x1 [T_TOK * C_DIM];
__device__ float g_ln2[T_TOK * C_DIM];
__device__ float g_fc1[T_TOK * HID];

// windowed-token row r -> original-layout token index (roll-back by +1,+3,+3)
__device__ __forceinline__ int remap_row(int r) {
    int b_ = r / NWIN, n = r - b_ * NWIN;
    int b    = b_ >> 8;
    int widx = b_ & 255;
    int dI = widx >> 6, hI = (widx >> 3) & 7, wI = widx & 7;
    int dd = n / 49, rem = n - dd * 49, hh = rem / 7, ww = rem - hh * 7;
    int ds = dI * 2 + dd, hs = hI * 7 + hh, ws = wI * 7 + ww;
    int d = (ds + 1) & 7;
    int h = hs + 3; if (h >= 56) h -= 56;
    int w = ws + 3; if (w >= 56) w -= 56;
    return ((b * 8 + d) * 56 + h) * 56 + w;
}

// ---------------------------------------------------------------------------
// LayerNorm over C=384; block per token, 128 threads.
// ---------------------------------------------------------------------------
template<bool REMAP>
__global__ void ln_kernel(const float* __restrict__ in,
                          const float* __restrict__ gw,
                          const float* __restrict__ gb,
                          float* __restrict__ out) {
    int r   = blockIdx.x;
    int tid = threadIdx.x;
    int src = REMAP ? remap_row(r) : r;
    const float* px = in + (size_t)src * C_DIM;

    float v[3];
    float sum = 0.f, sq = 0.f;
#pragma unroll
    for (int i = 0; i < 3; ++i) {
        float t = px[tid + i * 128];
        v[i] = t; sum += t; sq += t * t;
    }
#pragma unroll
    for (int o = 16; o > 0; o >>= 1) {
        sum += __shfl_xor_sync(0xffffffffu, sum, o);
        sq  += __shfl_xor_sync(0xffffffffu, sq,  o);
    }
    __shared__ float red[8];
    int warp = tid >> 5;
    if ((tid & 31) == 0) { red[warp] = sum; red[4 + warp] = sq; }
    __syncthreads();
    float ts = red[0] + red[1] + red[2] + red[3];
    float tq = red[4] + red[5] + red[6] + red[7];
    float mean = ts * (1.0f / C_DIM);
    float var  = tq * (1.0f / C_DIM) - mean * mean;
    float rstd = rsqrtf(var + 1e-5f);

    float* po = out + (size_t)r * C_DIM;
#pragma unroll
    for (int i = 0; i < 3; ++i) {
        int c = tid + i * 128;
        po[c] = (v[i] - mean) * rstd * gw[c] + gb[c];
    }
}

// ---------------------------------------------------------------------------
// TF32 tensor-core GEMM: C[M,N] = A[M,K] @ B[N,K]^T (+bias, epilogues)
// Block 128x128, BK=32, 256 threads = 8 warps (4x2), warp tile 32x64.
// EPI: 0=+bias  1=+bias,GELU  2=+bias,+res[row]  3=+bias,remap,+res[orig]
// ---------------------------------------------------------------------------
#define BM 128
#define BN 128
#define BK 32
#define LDT 36     // BK + 4 pad

template<int EPI>
__global__ __launch_bounds__(256, 2)
void gemm_wmma(const float* __restrict__ A, const float* __restrict__ B,
               const float* __restrict__ bias, float* __restrict__ Cmat,
               int M, int N, int K, const float* __restrict__ res) {
    __shared__ float As[BM][LDT];
    __shared__ float Bs[BN][LDT];
    __shared__ float Cs[8][16][20];   // per-warp epilogue staging (ld=20, mult of 4)

    const int tid  = threadIdx.x;
    const int warp = tid >> 5;
    const int lane = tid & 31;
    const int wm = warp >> 1;     // 0..3  -> rows wm*32
    const int wn = warp & 1;      // 0..1  -> cols wn*64
    const int m0 = blockIdx.y * BM, n0 = blockIdx.x * BN;

    wmma::fragment<wmma::accumulator, 16, 16, 8, float> acc[2][4];
#pragma unroll
    for (int i = 0; i < 2; ++i)
#pragma unroll
        for (int j = 0; j < 4; ++j) wmma::fill_fragment(acc[i][j], 0.0f);

    for (int k0 = 0; k0 < K; k0 += BK) {
#pragma unroll
        for (int l = 0; l < 4; ++l) {
            int f   = tid + l * 256;       // float4 index 0..1023
            int row = f >> 3;
            int col = (f & 7) * 4;
            *(float4*)&As[row][col] = *(const float4*)&A[(size_t)(m0 + row) * K + k0 + col];
            *(float4*)&Bs[row][col] = *(const float4*)&B[(size_t)(n0 + row) * K + k0 + col];
        }
        __syncthreads();
#pragma unroll
        for (int kk = 0; kk < BK; kk += 8) {
            wmma::fragment<wmma::matrix_a, 16, 16, 8, tf32_t, wmma::row_major> fa[2];
            wmma::fragment<wmma::matrix_b, 16, 16, 8, tf32_t, wmma::col_major> fb[4];
#pragma unroll
            for (int i = 0; i < 2; ++i) {
                wmma::load_matrix_sync(fa[i], &As[wm * 32 + i * 16][kk], LDT);
#pragma unroll
                for (int t = 0; t < fa[i].num_elements; ++t)
                    fa[i].x[t] = wmma::__float_to_tf32(fa[i].x[t]);
            }
#pragma unroll
            for (int j = 0; j < 4; ++j) {
                wmma::load_matrix_sync(fb[j], &Bs[wn * 64 + j * 16][kk], LDT);
#pragma unroll
                for (int t = 0; t < fb[j].num_elements; ++t)
                    fb[j].x[t] = wmma::__float_to_tf32(fb[j].x[t]);
            }
#pragma unroll
            for (int i = 0; i < 2; ++i)
#pragma unroll
                for (int j = 0; j < 4; ++j)
                    wmma::mma_sync(acc[i][j], fa[i], fb[j], acc[i][j]);
        }
        __syncthreads();
    }

    // epilogue via per-warp smem staging
#pragma unroll
    for (int i = 0; i < 2; ++i) {
#pragma unroll
        for (int j = 0; j < 4; ++j) {
            wmma::store_matrix_sync(&Cs[warp][0][0], acc[i][j], 20, wmma::mem_row_major);
            __syncwarp();
            int rbase = m0 + wm * 32 + i * 16;
            int cbase = n0 + wn * 64 + j * 16;
#pragma unroll
            for (int t = 0; t < 8; ++t) {
                int e  = t * 32 + lane;          // 0..255
                int rr = e >> 4, cc = e & 15;
                float v = Cs[warp][rr][cc];
                int r = rbase + rr, c = cbase + cc;
                v += bias[c];
                if (EPI == 1) v = 0.5f * v * (1.0f + erff(v * 0.70710678118654752f));
                size_t rowoff = (EPI == 3) ? (size_t)remap_row(r) * N : (size_t)r * N;
                if (EPI == 2 || EPI == 3) v += res[rowoff + c];
                Cmat[rowoff + c] = v;
            }
            __syncwarp();
        }
    }
}

// ---------------------------------------------------------------------------
// Attention: block per (window, head), 128 threads, 4x4 register tiling.
// smem: q,k,v as [100][36] (rows 98,99 zero) + scores [100][100].
// ---------------------------------------------------------------------------
#define QLD 36
__global__ void attn_kernel(const float* __restrict__ qkv,
                            const float* __restrict__ rpb,
                            float* __restrict__ out) {
    extern __shared__ float sm[];
    float* qs = sm;                    // 100*36
    float* ks = qs + 100 * QLD;
    float* vs = ks + 100 * QLD;
    float* sc = vs + 100 * QLD;        // 100*100

    int b_   = blockIdx.x;
    int head = blockIdx.y;
    int tid  = threadIdx.x;
    const float scale = 0.17677669529663687f;   // 32^-0.5

    size_t base = (size_t)b_ * NWIN * (3 * C_DIM) + head * HD;
    for (int idx = tid; idx < 100 * HD; idx += 128) {
        int m = idx >> 5, d = idx & 31;
        if (m < NWIN) {
            size_t o = base + (size_t)m * (3 * C_DIM) + d;
            qs[m * QLD + d] = qkv[o] * scale;
            ks[m * QLD + d] = qkv[o + C_DIM];
            vs[m * QLD + d] = qkv[o + 2 * C_DIM];
        } else {
            qs[m * QLD + d] = 0.f; ks[m * QLD + d] = 0.f; vs[m * QLD + d] = 0.f;
        }
    }
    __syncthreads();

    int widx = b_ & 255;
    int dI = widx >> 6, hI = (widx >> 3) & 7, wI = widx & 7;

    // scores: 25x25 tiles of 4x4
    for (int tt = tid; tt < 625; tt += 128) {
        int nt = tt / 25, mt = tt - nt * 25;
        float acc[4][4] = {};
#pragma unroll
        for (int d = 0; d < HD; d += 4) {
            float4 q[4], k[4];
#pragma unroll
            for (int i = 0; i < 4; ++i) q[i] = *(const float4*)&qs[(nt * 4 + i) * QLD + d];
#pragma unroll
            for (int j = 0; j < 4; ++j) k[j] = *(const float4*)&ks[(mt * 4 + j) * QLD + d];
#pragma unroll
            for (int i = 0; i < 4; ++i)
#pragma unroll
                for (int j = 0; j < 4; ++j)
                    acc[i][j] += q[i].x * k[j].x + q[i].y * k[j].y
                               + q[i].z * k[j].z + q[i].w * k[j].w;
        }
#pragma unroll
        for (int i = 0; i < 4; ++i) {
            int n = nt * 4 + i; if (n >= NWIN) continue;
            int nd = n / 49, nr = n - nd * 49, nh = nr / 7, nw = nr - nh * 7;
            int gdn = dI * 2 + nd, ghn = hI * 7 + nh, gwn = wI * 7 + nw;
            int ln = (gdn < 6 ? 0 : (gdn < 7 ? 1 : 2)) * 9
                   + (ghn < 49 ? 0 : (ghn < 53 ? 1 : 2)) * 3
                   + (gwn < 49 ? 0 : (gwn < 53 ? 1 : 2));
#pragma unroll
            for (int j = 0; j < 4; ++j) {
                int m = mt * 4 + j; if (m >= NWIN) continue;
                int md = m / 49, mr = m - md * 49, mh = mr / 7, mw = mr - mh * 7;
                int ridx = (nd - md + 1) * 169 + (nh - mh + 6) * 13 + (nw - mw + 6);
                float s = acc[i][j] + rpb[ridx * HEADS + head];
                int gdm = dI * 2 + md, ghm = hI * 7 + mh, gwm = wI * 7 + mw;
                int lm = (gdm < 6 ? 0 : (gdm < 7 ? 1 : 2)) * 9
                       + (ghm < 49 ? 0 : (ghm < 53 ? 1 : 2)) * 3
                       + (gwm < 49 ? 0 : (gwm < 53 ? 1 : 2));
                if (ln != lm) s -= 100.0f;
                sc[n * 100 + m] = s;
            }
        }
    }
    __syncthreads();

    // softmax rows
    if (tid < NWIN) {
        float mx = -1e30f;
        for (int m = 0; m < NWIN; ++m) mx = fmaxf(mx, sc[tid * 100 + m]);
        float sum = 0.f;
        for (int m = 0; m < NWIN; ++m) {
            float e = __expf(sc[tid * 100 + m] - mx);
            sc[tid * 100 + m] = e; sum += e;
        }
        float inv = 1.0f / sum;
        for (int m = 0; m < NWIN; ++m) sc[tid * 100 + m] *= inv;
    }
    __syncthreads();

    // A @ V : 25 n-tiles x 8 d-tiles, 4x4 register tiles
    for (int tt = tid; tt < 200; tt += 128) {
        int nt = tt >> 3, dt = tt & 7;
        float acc[4][4] = {};
        for (int m = 0; m < NWIN; ++m) {
            float4 v4 = *(const float4*)&vs[m * QLD + dt * 4];
#pragma unroll
            for (int i = 0; i < 4; ++i) {
                float s = sc[(nt * 4 + i) * 100 + m];
                acc[i][0] += s * v4.x; acc[i][1] += s * v4.y;
                acc[i][2] += s * v4.z; acc[i][3] += s * v4.w;
            }
        }
#pragma unroll
        for (int i = 0; i < 4; ++i) {
            int n = nt * 4 + i; if (n >= NWIN) continue;
            float4 o4 = make_float4(acc[i][0], acc[i][1], acc[i][2], acc[i][3]);
            *(float4*)&out[((size_t)b_ * NWIN + n) * C_DIM + head * HD + dt * 4] = o4;
        }
    }
}

// ---------------------------------------------------------------------------
// Launch sequence
// ---------------------------------------------------------------------------
extern "C" void kernel_launch(void* const* d_in, const int* in_sizes, int n_in,
                              void* d_out, int out_size) {
    const float* x     = (const float*)d_in[0];
    const float* n1w   = (const float*)d_in[1];
    const float* n1b   = (const float*)d_in[2];
    const float* qkvw  = (const float*)d_in[3];
    const float* qkvb  = (const float*)d_in[4];
    const float* rpb   = (const float*)d_in[5];
    const float* projw = (const float*)d_in[6];
    const float* projb = (const float*)d_in[7];
    const float* n2w   = (const float*)d_in[8];
    const float* n2b   = (const float*)d_in[9];
    const float* fc1w  = (const float*)d_in[10];
    const float* fc1b  = (const float*)d_in[11];
    const float* fc2w  = (const float*)d_in[12];
    const float* fc2b  = (const float*)d_in[13];
    float* out = (float*)d_out;

    float *xw, *qkv, *att, *x1, *ln2, *fc1;
    cudaGetSymbolAddress((void**)&xw,  g_xw);
    cudaGetSymbolAddress((void**)&qkv, g_qkv);
    cudaGetSymbolAddress((void**)&att, g_att);
    cudaGetSymbolAddress((void**)&x1,  g_x1);
    cudaGetSymbolAddress((void**)&ln2, g_ln2);
    cudaGetSymbolAddress((void**)&fc1, g_fc1);

    const int ATTN_SMEM = (3 * 100 * QLD + 100 * 100) * (int)sizeof(float); // 83200
    cudaFuncSetAttribute(attn_kernel, cudaFuncAttributeMaxDynamicSharedMemorySize, ATTN_SMEM);

    // 1. LN1 + shift + window partition
    ln_kernel<true><<<T_TOK, 128>>>(x, n1w, n1b, xw);

    // 2. QKV projection
    gemm_wmma<0><<<dim3(1152 / 128, T_TOK / 128), 256>>>(xw, qkvw, qkvb, qkv,
                                                         T_TOK, 3 * C_DIM, C_DIM, nullptr);

    // 3. Windowed attention
    attn_kernel<<<dim3(BWIN, HEADS), 128, ATTN_SMEM>>>(qkv, rpb, att);

    // 4. Proj + window reverse + roll back + shortcut
    gemm_wmma<3><<<dim3(C_DIM / 128, T_TOK / 128), 256>>>(att, projw, projb, x1,
                                                          T_TOK, C_DIM, C_DIM, x);

    // 5. LN2
    ln_kernel<false><<<T_TOK, 128>>>(x1, n2w, n2b, ln2);

    // 6. FC1 + exact GELU
    gemm_wmma<1><<<dim3(HID / 128, T_TOK / 128), 256>>>(ln2, fc1w, fc1b, fc1,
                                                        T_TOK, HID, C_DIM, nullptr);

    // 7. FC2 + residual -> d_out
    gemm_wmma<2><<<dim3(C_DIM / 128, T_TOK / 128), 256>>>(fc1, fc2w, fc2b, out,
                                                          T_TOK, C_DIM, HID, x1);
}

// round 3
// speedup vs baseline: 2.1171x; 1.0612x over previous
#include <cuda_runtime.h>
#include <math.h>
#include <mma.h>

using namespace nvcuda;
using tf32_t = wmma::precision::tf32;

#define T_TOK   50176
#define C_DIM   384
#define HEADS   12
#define HD      32
#define NWIN    98
#define BWIN    512
#define HID     1536

// Scratch (device globals: allocation-free rule)
__device__ float g_xw [T_TOK * C_DIM];
__device__ float g_qkv[T_TOK * 3 * C_DIM];
__device__ float g_att[T_TOK * C_DIM];
__device__ float g_x1 [T_TOK * C_DIM];
__device__ float g_ln2[T_TOK * C_DIM];
__device__ float g_fc1[T_TOK * HID];

__device__ __forceinline__ int remap_row(int r) {
    int b_ = r / NWIN, n = r - b_ * NWIN;
    int b    = b_ >> 8;
    int widx = b_ & 255;
    int dI = widx >> 6, hI = (widx >> 3) & 7, wI = widx & 7;
    int dd = n / 49, rem = n - dd * 49, hh = rem / 7, ww = rem - hh * 7;
    int ds = dI * 2 + dd, hs = hI * 7 + hh, ws = wI * 7 + ww;
    int d = (ds + 1) & 7;
    int h = hs + 3; if (h >= 56) h -= 56;
    int w = ws + 3; if (w >= 56) w -= 56;
    return ((b * 8 + d) * 56 + h) * 56 + w;
}

__device__ __forceinline__ void cp16(void* s, const void* g) {
    unsigned sa = (unsigned)__cvta_generic_to_shared(s);
    asm volatile("cp.async.cg.shared.global [%0], [%1], 16;\n" :: "r"(sa), "l"(g));
}
#define CP_COMMIT() asm volatile("cp.async.commit_group;\n" ::: "memory")
#define CP_WAIT0()  asm volatile("cp.async.wait_group 0;\n" ::: "memory")

// ---------------------------------------------------------------------------
// LayerNorm over C=384; block per token, 128 threads.
// ---------------------------------------------------------------------------
template<bool REMAP>
__global__ void ln_kernel(const float* __restrict__ in,
                          const float* __restrict__ gw,
                          const float* __restrict__ gb,
                          float* __restrict__ out) {
    int r   = blockIdx.x;
    int tid = threadIdx.x;
    int src = REMAP ? remap_row(r) : r;
    const float* px = in + (size_t)src * C_DIM;

    float v[3];
    float sum = 0.f, sq = 0.f;
#pragma unroll
    for (int i = 0; i < 3; ++i) {
        float t = px[tid + i * 128];
        v[i] = t; sum += t; sq += t * t;
    }
#pragma unroll
    for (int o = 16; o > 0; o >>= 1) {
        sum += __shfl_xor_sync(0xffffffffu, sum, o);
        sq  += __shfl_xor_sync(0xffffffffu, sq,  o);
    }
    __shared__ float red[8];
    int warp = tid >> 5;
    if ((tid & 31) == 0) { red[warp] = sum; red[4 + warp] = sq; }
    __syncthreads();
    float ts = red[0] + red[1] + red[2] + red[3];
    float tq = red[4] + red[5] + red[6] + red[7];
    float mean = ts * (1.0f / C_DIM);
    float var  = tq * (1.0f / C_DIM) - mean * mean;
    float rstd = rsqrtf(var + 1e-5f);

    float* po = out + (size_t)r * C_DIM;
#pragma unroll
    for (int i = 0; i < 3; ++i) {
        int c = tid + i * 128;
        po[c] = (v[i] - mean) * rstd * gw[c] + gb[c];
    }
}

// ---------------------------------------------------------------------------
// TF32 tensor-core GEMM with cp.async double buffering.
// C[M,N] = A[M,K] @ B[N,K]^T (+bias, epilogues)
// Block 128x128, BK=32, 256 threads = 8 warps (4x2), warp tile 32x64.
// EPI: 0=+bias  1=+bias,GELU  2=+bias,+res[row]  3=+bias,remap,+res[orig]
// ---------------------------------------------------------------------------
#define BM 128
#define BN 128
#define BK 32
#define LDT 36
#define STAGE_F (128 * LDT)           // floats per tile buffer

template<int EPI>
__global__ __launch_bounds__(256, 2)
void gemm_wmma(const float* __restrict__ A, const float* __restrict__ B,
               const float* __restrict__ bias, float* __restrict__ Cmat,
               int M, int N, int K, const float* __restrict__ res) {
    extern __shared__ float sm[];
    float* smA = sm;                        // [2][128][LDT]
    float* smB = sm + 2 * STAGE_F;          // [2][128][LDT]
    float* smC = sm + 4 * STAGE_F;          // [8][16][20] epilogue staging

    const int tid  = threadIdx.x;
    const int warp = tid >> 5;
    const int lane = tid & 31;
    const int wm = warp >> 1;
    const int wn = warp & 1;
    const int m0 = blockIdx.y * BM, n0 = blockIdx.x * BN;

    wmma::fragment<wmma::accumulator, 16, 16, 8, float> acc[2][4];
#pragma unroll
    for (int i = 0; i < 2; ++i)
#pragma unroll
        for (int j = 0; j < 4; ++j) wmma::fill_fragment(acc[i][j], 0.0f);

    // per-thread load coords (4 float4 per matrix per stage)
    auto load_stage = [&](int stage, int k0) {
        float* as = smA + stage * STAGE_F;
        float* bs = smB + stage * STAGE_F;
#pragma unroll
        for (int l = 0; l < 4; ++l) {
            int f   = tid + l * 256;
            int row = f >> 3;
            int col = (f & 7) * 4;
            cp16(&as[row * LDT + col], &A[(size_t)(m0 + row) * K + k0 + col]);
            cp16(&bs[row * LDT + col], &B[(size_t)(n0 + row) * K + k0 + col]);
        }
        CP_COMMIT();
    };

    load_stage(0, 0);
    int buf = 0;
    for (int k0 = 0; k0 < K; k0 += BK) {
        CP_WAIT0();
        __syncthreads();
        if (k0 + BK < K) load_stage(buf ^ 1, k0 + BK);

        const float* as = smA + buf * STAGE_F;
        const float* bs = smB + buf * STAGE_F;
#pragma unroll
        for (int kk = 0; kk < BK; kk += 8) {
            wmma::fragment<wmma::matrix_a, 16, 16, 8, tf32_t, wmma::row_major> fa[2];
            wmma::fragment<wmma::matrix_b, 16, 16, 8, tf32_t, wmma::col_major> fb[4];
#pragma unroll
            for (int i = 0; i < 2; ++i)
                wmma::load_matrix_sync(fa[i], &as[(wm * 32 + i * 16) * LDT + kk], LDT);
#pragma unroll
            for (int j = 0; j < 4; ++j)
                wmma::load_matrix_sync(fb[j], &bs[(wn * 64 + j * 16) * LDT + kk], LDT);
#pragma unroll
            for (int i = 0; i < 2; ++i)
#pragma unroll
                for (int j = 0; j < 4; ++j)
                    wmma::mma_sync(acc[i][j], fa[i], fb[j], acc[i][j]);
        }
        buf ^= 1;
        __syncthreads();
    }

    // epilogue via per-warp smem staging
    float* cw = smC + warp * 16 * 20;
#pragma unroll
    for (int i = 0; i < 2; ++i) {
#pragma unroll
        for (int j = 0; j < 4; ++j) {
            wmma::store_matrix_sync(cw, acc[i][j], 20, wmma::mem_row_major);
            __syncwarp();
            int rbase = m0 + wm * 32 + i * 16;
            int cbase = n0 + wn * 64 + j * 16;
#pragma unroll
            for (int t = 0; t < 8; ++t) {
                int e  = t * 32 + lane;
                int rr = e >> 4, cc = e & 15;
                float v = cw[rr * 20 + cc];
                int r = rbase + rr, c = cbase + cc;
                v += bias[c];
                if (EPI == 1) v = 0.5f * v * (1.0f + erff(v * 0.70710678118654752f));
                size_t rowoff = (EPI == 3) ? (size_t)remap_row(r) * N : (size_t)r * N;
                if (EPI == 2 || EPI == 3) v += res[rowoff + c];
                Cmat[rowoff + c] = v;
            }
            __syncwarp();
        }
    }
}
#define GEMM_SMEM ((4 * STAGE_F + 8 * 16 * 20) * (int)sizeof(float))

// ---------------------------------------------------------------------------
// Attention: block per (window, head), 128 threads, 4x4 register tiling.
// ---------------------------------------------------------------------------
#define QLD 36
__global__ void attn_kernel(const float* __restrict__ qkv,
                            const float* __restrict__ rpb,
                            float* __restrict__ out) {
    extern __shared__ float sm[];
    float* qs = sm;
    float* ks = qs + 100 * QLD;
    float* vs = ks + 100 * QLD;
    float* sc = vs + 100 * QLD;

    int b_   = blockIdx.x;
    int head = blockIdx.y;
    int tid  = threadIdx.x;
    const float scale = 0.17677669529663687f;

    size_t base = (size_t)b_ * NWIN * (3 * C_DIM) + head * HD;
    for (int idx = tid; idx < 100 * HD; idx += 128) {
        int m = idx >> 5, d = idx & 31;
        if (m < NWIN) {
            size_t o = base + (size_t)m * (3 * C_DIM) + d;
            qs[m * QLD + d] = qkv[o] * scale;
            ks[m * QLD + d] = qkv[o + C_DIM];
            vs[m * QLD + d] = qkv[o + 2 * C_DIM];
        } else {
            qs[m * QLD + d] = 0.f; ks[m * QLD + d] = 0.f; vs[m * QLD + d] = 0.f;
        }
    }
    __syncthreads();

    int widx = b_ & 255;
    int dI = widx >> 6, hI = (widx >> 3) & 7, wI = widx & 7;

    for (int tt = tid; tt < 625; tt += 128) {
        int nt = tt / 25, mt = tt - nt * 25;
        float acc[4][4] = {};
#pragma unroll
        for (int d = 0; d < HD; d += 4) {
            float4 q[4], k[4];
#pragma unroll
            for (int i = 0; i < 4; ++i) q[i] = *(const float4*)&qs[(nt * 4 + i) * QLD + d];
#pragma unroll
            for (int j = 0; j < 4; ++j) k[j] = *(const float4*)&ks[(mt * 4 + j) * QLD + d];
#pragma unroll
            for (int i = 0; i < 4; ++i)
#pragma unroll
                for (int j = 0; j < 4; ++j)
                    acc[i][j] += q[i].x * k[j].x + q[i].y * k[j].y
                               + q[i].z * k[j].z + q[i].w * k[j].w;
        }
#pragma unroll
        for (int i = 0; i < 4; ++i) {
            int n = nt * 4 + i; if (n >= NWIN) continue;
            int nd = n / 49, nr = n - nd * 49, nh = nr / 7, nw = nr - nh * 7;
            int gdn = dI * 2 + nd, ghn = hI * 7 + nh, gwn = wI * 7 + nw;
            int ln = (gdn < 6 ? 0 : (gdn < 7 ? 1 : 2)) * 9
                   + (ghn < 49 ? 0 : (ghn < 53 ? 1 : 2)) * 3
                   + (gwn < 49 ? 0 : (gwn < 53 ? 1 : 2));
#pragma unroll
            for (int j = 0; j < 4; ++j) {
                int m = mt * 4 + j; if (m >= NWIN) continue;
                int md = m / 49, mr = m - md * 49, mh = mr / 7, mw = mr - mh * 7;
                int ridx = (nd - md + 1) * 169 + (nh - mh + 6) * 13 + (nw - mw + 6);
                float s = acc[i][j] + rpb[ridx * HEADS + head];
                int gdm = dI * 2 + md, ghm = hI * 7 + mh, gwm = wI * 7 + mw;
                int lm = (gdm < 6 ? 0 : (gdm < 7 ? 1 : 2)) * 9
                       + (ghm < 49 ? 0 : (ghm < 53 ? 1 : 2)) * 3
                       + (gwm < 49 ? 0 : (gwm < 53 ? 1 : 2));
                if (ln != lm) s -= 100.0f;
                sc[n * 100 + m] = s;
            }
        }
    }
    __syncthreads();

    if (tid < NWIN) {
        float mx = -1e30f;
        for (int m = 0; m < NWIN; ++m) mx = fmaxf(mx, sc[tid * 100 + m]);
        float sum = 0.f;
        for (int m = 0; m < NWIN; ++m) {
            float e = __expf(sc[tid * 100 + m] - mx);
            sc[tid * 100 + m] = e; sum += e;
        }
        float inv = 1.0f / sum;
        for (int m = 0; m < NWIN; ++m) sc[tid * 100 + m] *= inv;
    }
    __syncthreads();

    for (int tt = tid; tt < 200; tt += 128) {
        int nt = tt >> 3, dt = tt & 7;
        float acc[4][4] = {};
        for (int m = 0; m < NWIN; ++m) {
            float4 v4 = *(const float4*)&vs[m * QLD + dt * 4];
#pragma unroll
            for (int i = 0; i < 4; ++i) {
                float s = sc[(nt * 4 + i) * 100 + m];
                acc[i][0] += s * v4.x; acc[i][1] += s * v4.y;
                acc[i][2] += s * v4.z; acc[i][3] += s * v4.w;
            }
        }
#pragma unroll
        for (int i = 0; i < 4; ++i) {
            int n = nt * 4 + i; if (n >= NWIN) continue;
            float4 o4 = make_float4(acc[i][0], acc[i][1], acc[i][2], acc[i][3]);
            *(float4*)&out[((size_t)b_ * NWIN + n) * C_DIM + head * HD + dt * 4] = o4;
        }
    }
}

// ---------------------------------------------------------------------------
extern "C" void kernel_launch(void* const* d_in, const int* in_sizes, int n_in,
                              void* d_out, int out_size) {
    const float* x     = (const float*)d_in[0];
    const float* n1w   = (const float*)d_in[1];
    const float* n1b   = (const float*)d_in[2];
    const float* qkvw  = (const float*)d_in[3];
    const float* qkvb  = (const float*)d_in[4];
    const float* rpb   = (const float*)d_in[5];
    const float* projw = (const float*)d_in[6];
    const float* projb = (const float*)d_in[7];
    const float* n2w   = (const float*)d_in[8];
    const float* n2b   = (const float*)d_in[9];
    const float* fc1w  = (const float*)d_in[10];
    const float* fc1b  = (const float*)d_in[11];
    const float* fc2w  = (const float*)d_in[12];
    const float* fc2b  = (const float*)d_in[13];
    float* out = (float*)d_out;

    float *xw, *qkv, *att, *x1, *ln2, *fc1;
    cudaGetSymbolAddress((void**)&xw,  g_xw);
    cudaGetSymbolAddress((void**)&qkv, g_qkv);
    cudaGetSymbolAddress((void**)&att, g_att);
    cudaGetSymbolAddress((void**)&x1,  g_x1);
    cudaGetSymbolAddress((void**)&ln2, g_ln2);
    cudaGetSymbolAddress((void**)&fc1, g_fc1);

    const int ATTN_SMEM = (3 * 100 * QLD + 100 * 100) * (int)sizeof(float);
    cudaFuncSetAttribute(attn_kernel, cudaFuncAttributeMaxDynamicSharedMemorySize, ATTN_SMEM);
    cudaFuncSetAttribute(gemm_wmma<0>, cudaFuncAttributeMaxDynamicSharedMemorySize, GEMM_SMEM);
    cudaFuncSetAttribute(gemm_wmma<1>, cudaFuncAttributeMaxDynamicSharedMemorySize, GEMM_SMEM);
    cudaFuncSetAttribute(gemm_wmma<2>, cudaFuncAttributeMaxDynamicSharedMemorySize, GEMM_SMEM);
    cudaFuncSetAttribute(gemm_wmma<3>, cudaFuncAttributeMaxDynamicSharedMemorySize, GEMM_SMEM);

    ln_kernel<true><<<T_TOK, 128>>>(x, n1w, n1b, xw);

    gemm_wmma<0><<<dim3(1152 / 128, T_TOK / 128), 256, GEMM_SMEM>>>(
        xw, qkvw, qkvb, qkv, T_TOK, 3 * C_DIM, C_DIM, nullptr);

    attn_kernel<<<dim3(BWIN, HEADS), 128, ATTN_SMEM>>>(qkv, rpb, att);

    gemm_wmma<3><<<dim3(C_DIM / 128, T_TOK / 128), 256, GEMM_SMEM>>>(
        att, projw, projb, x1, T_TOK, C_DIM, C_DIM, x);

    ln_kernel<false><<<T_TOK, 128>>>(x1, n2w, n2b, ln2);

    gemm_wmma<1><<<dim3(HID / 128, T_TOK / 128), 256, GEMM_SMEM>>>(
        ln2, fc1w, fc1b, fc1, T_TOK, HID, C_DIM, nullptr);

    gemm_wmma<2><<<dim3(C_DIM / 128, T_TOK / 128), 256, GEMM_SMEM>>>(
        fc1, fc2w, fc2b, out, T_TOK, C_DIM, HID, x1);
}

// round 4
// speedup vs baseline: 4.4913x; 2.1215x over previous
#include <cuda_runtime.h>
#include <cuda_fp16.h>
#include <math.h>
#include <mma.h>

using namespace nvcuda;

#define T_TOK   50176
#define C_DIM   384
#define HEADS   12
#define HD      32
#define NWIN    98
#define BWIN    512
#define HID     1536

// Scratch (device globals: allocation-free rule)
__device__ __half g_xw [T_TOK * C_DIM];        // LN1+shift+partition (half)
__device__ float  g_qkv[T_TOK * 3 * C_DIM];    // qkv output (fp32)
__device__ __half g_att[T_TOK * C_DIM];        // attention out (half)
__device__ float  g_x1 [T_TOK * C_DIM];        // x + attn branch (fp32)
__device__ __half g_ln2[T_TOK * C_DIM];        // LN2 (half)
__device__ __half g_fc1[T_TOK * HID];          // gelu(fc1) (half)
// half weight copies
__device__ __half g_qkvw[3 * C_DIM * C_DIM];
__device__ __half g_projw[C_DIM * C_DIM];
__device__ __half g_fc1w[HID * C_DIM];
__device__ __half g_fc2w[C_DIM * HID];

__device__ __forceinline__ int remap_row(int r) {
    int b_ = r / NWIN, n = r - b_ * NWIN;
    int b    = b_ >> 8;
    int widx = b_ & 255;
    int dI = widx >> 6, hI = (widx >> 3) & 7, wI = widx & 7;
    int dd = n / 49, rem = n - dd * 49, hh = rem / 7, ww = rem - hh * 7;
    int ds = dI * 2 + dd, hs = hI * 7 + hh, ws = wI * 7 + ww;
    int d = (ds + 1) & 7;
    int h = hs + 3; if (h >= 56) h -= 56;
    int w = ws + 3; if (w >= 56) w -= 56;
    return ((b * 8 + d) * 56 + h) * 56 + w;
}

__device__ __forceinline__ void cp16(void* s, const void* g) {
    unsigned sa = (unsigned)__cvta_generic_to_shared(s);
    asm volatile("cp.async.cg.shared.global [%0], [%1], 16;\n" :: "r"(sa), "l"(g));
}
#define CP_COMMIT() asm volatile("cp.async.commit_group;\n" ::: "memory")
#define CP_WAIT1()  asm volatile("cp.async.wait_group 1;\n" ::: "memory")
#define CP_WAIT0()  asm volatile("cp.async.wait_group 0;\n" ::: "memory")

// f32 -> f16 conversion (weights)
__global__ void cvt_kernel(const float* __restrict__ in, __half* __restrict__ out, int n) {
    int i = blockIdx.x * 256 + threadIdx.x;
    if (i < n) out[i] = __float2half(in[i]);
}

// ---------------------------------------------------------------------------
// LayerNorm over C=384; block per token, 128 threads; half output.
// ---------------------------------------------------------------------------
template<bool REMAP>
__global__ void ln_kernel(const float* __restrict__ in,
                          const float* __restrict__ gw,
                          const float* __restrict__ gb,
                          __half* __restrict__ out) {
    int r   = blockIdx.x;
    int tid = threadIdx.x;
    int src = REMAP ? remap_row(r) : r;
    const float* px = in + (size_t)src * C_DIM;

    float v[3];
    float sum = 0.f, sq = 0.f;
#pragma unroll
    for (int i = 0; i < 3; ++i) {
        float t = px[tid + i * 128];
        v[i] = t; sum += t; sq += t * t;
    }
#pragma unroll
    for (int o = 16; o > 0; o >>= 1) {
        sum += __shfl_xor_sync(0xffffffffu, sum, o);
        sq  += __shfl_xor_sync(0xffffffffu, sq,  o);
    }
    __shared__ float red[8];
    int warp = tid >> 5;
    if ((tid & 31) == 0) { red[warp] = sum; red[4 + warp] = sq; }
    __syncthreads();
    float ts = red[0] + red[1] + red[2] + red[3];
    float tq = red[4] + red[5] + red[6] + red[7];
    float mean = ts * (1.0f / C_DIM);
    float var  = tq * (1.0f / C_DIM) - mean * mean;
    float rstd = rsqrtf(var + 1e-5f);

    __half* po = out + (size_t)r * C_DIM;
#pragma unroll
    for (int i = 0; i < 3; ++i) {
        int c = tid + i * 128;
        po[c] = __float2half((v[i] - mean) * rstd * gw[c] + gb[c]);
    }
}

// ---------------------------------------------------------------------------
// FP16 tensor-core GEMM, 3-stage cp.async pipeline.
// C[M,N] = A[M,K] @ B[N,K]^T (+bias, epilogues)
// Block 128x128, BK=32, 256 threads = 8 warps (4x2), warp tile 32x64.
// EPI: 0=+bias(f32 out)  1=+bias,GELU(half out)  2=+bias,+res(f32 out)
//      3=+bias,remap,+res[orig](f32 out)
// ---------------------------------------------------------------------------
#define BM 128
#define BN 128
#define BK 32
#define LDH 40                         // halves per row (32 + 8 pad)
#define STAGE_H (128 * LDH)            // halves per tile buffer

template<int EPI, typename OutT>
__global__ __launch_bounds__(256, 2)
void gemm_h(const __half* __restrict__ A, const __half* __restrict__ B,
            const float* __restrict__ bias, OutT* __restrict__ Cmat,
            int M, int N, int K, const float* __restrict__ res) {
    extern __shared__ __half smh[];
    __half* smA = smh;                       // [3][128][LDH]
    __half* smB = smh + 3 * STAGE_H;         // [3][128][LDH]
    float*  smC = (float*)smh;               // epilogue staging (overlaps stage 0)

    const int tid  = threadIdx.x;
    const int warp = tid >> 5;
    const int lane = tid & 31;
    const int wm = warp >> 1;
    const int wn = warp & 1;
    const int m0 = blockIdx.y * BM, n0 = blockIdx.x * BN;

    wmma::fragment<wmma::accumulator, 16, 16, 16, float> acc[2][4];
#pragma unroll
    for (int i = 0; i < 2; ++i)
#pragma unroll
        for (int j = 0; j < 4; ++j) wmma::fill_fragment(acc[i][j], 0.0f);

    auto load_stage = [&](int stage, int k0) {
        __half* as = smA + stage * STAGE_H;
        __half* bs = smB + stage * STAGE_H;
#pragma unroll
        for (int l = 0; l < 2; ++l) {
            int f   = tid + l * 256;            // 0..511
            int row = f >> 2;
            int col = (f & 3) * 8;
            cp16(&as[row * LDH + col], &A[(size_t)(m0 + row) * K + k0 + col]);
            cp16(&bs[row * LDH + col], &B[(size_t)(n0 + row) * K + k0 + col]);
        }
        CP_COMMIT();
    };

    const int nt = K / BK;
    load_stage(0, 0);
    load_stage(1, BK);

    for (int t = 0; t < nt; ++t) {
        if (t + 1 < nt) { CP_WAIT1(); } else { CP_WAIT0(); }
        __syncthreads();

        const __half* as = smA + (t % 3) * STAGE_H;
        const __half* bs = smB + (t % 3) * STAGE_H;
#pragma unroll
        for (int kk = 0; kk < BK; kk += 16) {
            wmma::fragment<wmma::matrix_a, 16, 16, 16, __half, wmma::row_major> fa[2];
            wmma::fragment<wmma::matrix_b, 16, 16, 16, __half, wmma::col_major> fb[4];
#pragma unroll
            for (int i = 0; i < 2; ++i)
                wmma::load_matrix_sync(fa[i], &as[(wm * 32 + i * 16) * LDH + kk], LDH);
#pragma unroll
            for (int j = 0; j < 4; ++j)
                wmma::load_matrix_sync(fb[j], &bs[(wn * 64 + j * 16) * LDH + kk], LDH);
#pragma unroll
            for (int i = 0; i < 2; ++i)
#pragma unroll
                for (int j = 0; j < 4; ++j)
                    wmma::mma_sync(acc[i][j], fa[i], fb[j], acc[i][j]);
        }
        if (t + 2 < nt) load_stage((t + 2) % 3, (t + 2) * BK);
        __syncthreads();
    }

    // epilogue via per-warp smem staging (overlaps pipeline buffers; loop is done)
    float* cw = smC + warp * 16 * 20;
#pragma unroll
    for (int i = 0; i < 2; ++i) {
#pragma unroll
        for (int j = 0; j < 4; ++j) {
            wmma::store_matrix_sync(cw, acc[i][j], 20, wmma::mem_row_major);
            __syncwarp();
            int rbase = m0 + wm * 32 + i * 16;
            int cbase = n0 + wn * 64 + j * 16;
#pragma unroll
            for (int t = 0; t < 8; ++t) {
                int e  = t * 32 + lane;
                int rr = e >> 4, cc = e & 15;
                float v = cw[rr * 20 + cc];
                int r = rbase + rr, c = cbase + cc;
                v += bias[c];
                if (EPI == 1) v = 0.5f * v * (1.0f + erff(v * 0.70710678118654752f));
                size_t rowoff = (EPI == 3) ? (size_t)remap_row(r) * N : (size_t)r * N;
                if (EPI == 2 || EPI == 3) v += res[rowoff + c];
                Cmat[rowoff + c] = (OutT)v;
            }
            __syncwarp();
        }
    }
}
#define GEMM_SMEM (6 * STAGE_H * (int)sizeof(__half))   // 61440

// ---------------------------------------------------------------------------
// Attention: block per (window, head), 128 threads, 4x4 register tiling.
// ---------------------------------------------------------------------------
#define QLD 36
__global__ void attn_kernel(const float* __restrict__ qkv,
                            const float* __restrict__ rpb,
                            __half* __restrict__ out) {
    extern __shared__ float sm[];
    float* qs = sm;
    float* ks = qs + 100 * QLD;
    float* vs = ks + 100 * QLD;
    float* sc = vs + 100 * QLD;

    int b_   = blockIdx.x;
    int head = blockIdx.y;
    int tid  = threadIdx.x;
    const float scale = 0.17677669529663687f;

    size_t base = (size_t)b_ * NWIN * (3 * C_DIM) + head * HD;
    for (int idx = tid; idx < 100 * HD; idx += 128) {
        int m = idx >> 5, d = idx & 31;
        if (m < NWIN) {
            size_t o = base + (size_t)m * (3 * C_DIM) + d;
            qs[m * QLD + d] = qkv[o] * scale;
            ks[m * QLD + d] = qkv[o + C_DIM];
            vs[m * QLD + d] = qkv[o + 2 * C_DIM];
        } else {
            qs[m * QLD + d] = 0.f; ks[m * QLD + d] = 0.f; vs[m * QLD + d] = 0.f;
        }
    }
    __syncthreads();

    int widx = b_ & 255;
    int dI = widx >> 6, hI = (widx >> 3) & 7, wI = widx & 7;

    for (int tt = tid; tt < 625; tt += 128) {
        int nt = tt / 25, mt = tt - nt * 25;
        float acc[4][4] = {};
#pragma unroll
        for (int d = 0; d < HD; d += 4) {
            float4 q[4], k[4];
#pragma unroll
            for (int i = 0; i < 4; ++i) q[i] = *(const float4*)&qs[(nt * 4 + i) * QLD + d];
#pragma unroll
            for (int j = 0; j < 4; ++j) k[j] = *(const float4*)&ks[(mt * 4 + j) * QLD + d];
#pragma unroll
            for (int i = 0; i < 4; ++i)
#pragma unroll
                for (int j = 0; j < 4; ++j)
                    acc[i][j] += q[i].x * k[j].x + q[i].y * k[j].y
                               + q[i].z * k[j].z + q[i].w * k[j].w;
        }
#pragma unroll
        for (int i = 0; i < 4; ++i) {
            int n = nt * 4 + i; if (n >= NWIN) continue;
            int nd = n / 49, nr = n - nd * 49, nh = nr / 7, nw = nr - nh * 7;
            int gdn = dI * 2 + nd, ghn = hI * 7 + nh, gwn = wI * 7 + nw;
            int ln = (gdn < 6 ? 0 : (gdn < 7 ? 1 : 2)) * 9
                   + (ghn < 49 ? 0 : (ghn < 53 ? 1 : 2)) * 3
                   + (gwn < 49 ? 0 : (gwn < 53 ? 1 : 2));
#pragma unroll
            for (int j = 0; j < 4; ++j) {
                int m = mt * 4 + j; if (m >= NWIN) continue;
                int md = m / 49, mr = m - md * 49, mh = mr / 7, mw = mr - mh * 7;
                int ridx = (nd - md + 1) * 169 + (nh - mh + 6) * 13 + (nw - mw + 6);
                float s = acc[i][j] + rpb[ridx * HEADS + head];
                int gdm = dI * 2 + md, ghm = hI * 7 + mh, gwm = wI * 7 + mw;
                int lm = (gdm < 6 ? 0 : (gdm < 7 ? 1 : 2)) * 9
                       + (ghm < 49 ? 0 : (ghm < 53 ? 1 : 2)) * 3
                       + (gwm < 49 ? 0 : (gwm < 53 ? 1 : 2));
                if (ln != lm) s -= 100.0f;
                sc[n * 100 + m] = s;
            }
        }
    }
    __syncthreads();

    if (tid < NWIN) {
        float mx = -1e30f;
        for (int m = 0; m < NWIN; ++m) mx = fmaxf(mx, sc[tid * 100 + m]);
        float sum = 0.f;
        for (int m = 0; m < NWIN; ++m) {
            float e = __expf(sc[tid * 100 + m] - mx);
            sc[tid * 100 + m] = e; sum += e;
        }
        float inv = 1.0f / sum;
        for (int m = 0; m < NWIN; ++m) sc[tid * 100 + m] *= inv;
    }
    __syncthreads();

    for (int tt = tid; tt < 200; tt += 128) {
        int nt = tt >> 3, dt = tt & 7;
        float acc[4][4] = {};
        for (int m = 0; m < NWIN; ++m) {
            float4 v4 = *(const float4*)&vs[m * QLD + dt * 4];
#pragma unroll
            for (int i = 0; i < 4; ++i) {
                float s = sc[(nt * 4 + i) * 100 + m];
                acc[i][0] += s * v4.x; acc[i][1] += s * v4.y;
                acc[i][2] += s * v4.z; acc[i][3] += s * v4.w;
            }
        }
#pragma unroll
        for (int i = 0; i < 4; ++i) {
            int n = nt * 4 + i; if (n >= NWIN) continue;
            __half2 h01 = __floats2half2_rn(acc[i][0], acc[i][1]);
            __half2 h23 = __floats2half2_rn(acc[i][2], acc[i][3]);
            __half2* po = (__half2*)&out[((size_t)b_ * NWIN + n) * C_DIM + head * HD + dt * 4];
            po[0] = h01; po[1] = h23;
        }
    }
}

// ---------------------------------------------------------------------------
extern "C" void kernel_launch(void* const* d_in, const int* in_sizes, int n_in,
                              void* d_out, int out_size) {
    const float* x     = (const float*)d_in[0];
    const float* n1w   = (const float*)d_in[1];
    const float* n1b   = (const float*)d_in[2];
    const float* qkvw  = (const float*)d_in[3];
    const float* qkvb  = (const float*)d_in[4];
    const float* rpb   = (const float*)d_in[5];
    const float* projw = (const float*)d_in[6];
    const float* projb = (const float*)d_in[7];
    const float* n2w   = (const float*)d_in[8];
    const float* n2b   = (const float*)d_in[9];
    const float* fc1w  = (const float*)d_in[10];
    const float* fc1b  = (const float*)d_in[11];
    const float* fc2w  = (const float*)d_in[12];
    const float* fc2b  = (const float*)d_in[13];
    float* out = (float*)d_out;

    __half *xw, *att, *ln2, *fc1, *qkvwh, *projwh, *fc1wh, *fc2wh;
    float *qkv, *x1;
    cudaGetSymbolAddress((void**)&xw,    g_xw);
    cudaGetSymbolAddress((void**)&qkv,   g_qkv);
    cudaGetSymbolAddress((void**)&att,   g_att);
    cudaGetSymbolAddress((void**)&x1,    g_x1);
    cudaGetSymbolAddress((void**)&ln2,   g_ln2);
    cudaGetSymbolAddress((void**)&fc1,   g_fc1);
    cudaGetSymbolAddress((void**)&qkvwh, g_qkvw);
    cudaGetSymbolAddress((void**)&projwh,g_projw);
    cudaGetSymbolAddress((void**)&fc1wh, g_fc1w);
    cudaGetSymbolAddress((void**)&fc2wh, g_fc2w);

    const int ATTN_SMEM = (3 * 100 * QLD + 100 * 100) * (int)sizeof(float);
    cudaFuncSetAttribute(attn_kernel, cudaFuncAttributeMaxDynamicSharedMemorySize, ATTN_SMEM);
    cudaFuncSetAttribute(gemm_h<0,float>,  cudaFuncAttributeMaxDynamicSharedMemorySize, GEMM_SMEM);
    cudaFuncSetAttribute(gemm_h<1,__half>, cudaFuncAttributeMaxDynamicSharedMemorySize, GEMM_SMEM);
    cudaFuncSetAttribute(gemm_h<2,float>,  cudaFuncAttributeMaxDynamicSharedMemorySize, GEMM_SMEM);
    cudaFuncSetAttribute(gemm_h<3,float>,  cudaFuncAttributeMaxDynamicSharedMemorySize, GEMM_SMEM);

    // 0. weight conversions (cheap)
    cvt_kernel<<<(3*C_DIM*C_DIM + 255)/256, 256>>>(qkvw, qkvwh, 3*C_DIM*C_DIM);
    cvt_kernel<<<(C_DIM*C_DIM   + 255)/256, 256>>>(projw, projwh, C_DIM*C_DIM);
    cvt_kernel<<<(HID*C_DIM     + 255)/256, 256>>>(fc1w, fc1wh, HID*C_DIM);
    cvt_kernel<<<(C_DIM*HID     + 255)/256, 256>>>(fc2w, fc2wh, C_DIM*HID);

    // 1. LN1 + shift + window partition (half out)
    ln_kernel<true><<<T_TOK, 128>>>(x, n1w, n1b, xw);

    // 2. QKV projection (fp32 out)
    gemm_h<0,float><<<dim3(1152/128, T_TOK/128), 256, GEMM_SMEM>>>(
        xw, qkvwh, qkvb, qkv, T_TOK, 3*C_DIM, C_DIM, nullptr);

    // 3. Windowed attention (half out)
    attn_kernel<<<dim3(BWIN, HEADS), 128, ATTN_SMEM>>>(qkv, rpb, att);

    // 4. Proj + reverse + shortcut (fp32 out)
    gemm_h<3,float><<<dim3(C_DIM/128, T_TOK/128), 256, GEMM_SMEM>>>(
        att, projwh, projb, x1, T_TOK, C_DIM, C_DIM, x);

    // 5. LN2 (half out)
    ln_kernel<false><<<T_TOK, 128>>>(x1, n2w, n2b, ln2);

    // 6. FC1 + GELU (half out)
    gemm_h<1,__half><<<dim3(HID/128, T_TOK/128), 256, GEMM_SMEM>>>(
        ln2, fc1wh, fc1b, fc1, T_TOK, HID, C_DIM, nullptr);

    // 7. FC2 + residual (fp32 out -> d_out)
    gemm_h<2,float><<<dim3(C_DIM/128, T_TOK/128), 256, GEMM_SMEM>>>(
        fc1, fc2wh, fc2b, out, T_TOK, C_DIM, HID, x1);
}

// round 5
// speedup vs baseline: 6.4475x; 1.4355x over previous
#include <cuda_runtime.h>
#include <cuda_fp16.h>
#include <math.h>
#include <mma.h>

using namespace nvcuda;

#define T_TOK   50176
#define C_DIM   384
#define HEADS   12
#define HD      32
#define NWIN    98
#define BWIN    512
#define HID     1536

// Scratch (device globals: allocation-free rule)
__device__ __half g_xw [T_TOK * C_DIM];        // LN1+shift+partition (half)
__device__ __half g_qkv[T_TOK * 3 * C_DIM];    // qkv output (half)
__device__ __half g_att[T_TOK * C_DIM];        // attention out (half)
__device__ float  g_x1 [T_TOK * C_DIM];        // x + attn branch (fp32)
__device__ __half g_ln2[T_TOK * C_DIM];        // LN2 (half)
__device__ __half g_fc1[T_TOK * HID];          // gelu(fc1) (half)
// half weight copies
__device__ __half g_qkvw[3 * C_DIM * C_DIM];
__device__ __half g_projw[C_DIM * C_DIM];
__device__ __half g_fc1w[HID * C_DIM];
__device__ __half g_fc2w[C_DIM * HID];

__device__ __forceinline__ int remap_row(int r) {
    int b_ = r / NWIN, n = r - b_ * NWIN;
    int b    = b_ >> 8;
    int widx = b_ & 255;
    int dI = widx >> 6, hI = (widx >> 3) & 7, wI = widx & 7;
    int dd = n / 49, rem = n - dd * 49, hh = rem / 7, ww = rem - hh * 7;
    int ds = dI * 2 + dd, hs = hI * 7 + hh, ws = wI * 7 + ww;
    int d = (ds + 1) & 7;
    int h = hs + 3; if (h >= 56) h -= 56;
    int w = ws + 3; if (w >= 56) w -= 56;
    return ((b * 8 + d) * 56 + h) * 56 + w;
}

__device__ __forceinline__ void cp16(void* s, const void* g) {
    unsigned sa = (unsigned)__cvta_generic_to_shared(s);
    asm volatile("cp.async.cg.shared.global [%0], [%1], 16;\n" :: "r"(sa), "l"(g));
}
#define CP_COMMIT() asm volatile("cp.async.commit_group;\n" ::: "memory")
#define CP_WAIT1()  asm volatile("cp.async.wait_group 1;\n" ::: "memory")
#define CP_WAIT0()  asm volatile("cp.async.wait_group 0;\n" ::: "memory")

__global__ void cvt_kernel(const float* __restrict__ in, __half* __restrict__ out, int n) {
    int i = blockIdx.x * 256 + threadIdx.x;
    if (i < n) out[i] = __float2half(in[i]);
}

// ---------------------------------------------------------------------------
// LayerNorm over C=384; block per token, 128 threads; half output.
// ---------------------------------------------------------------------------
template<bool REMAP>
__global__ void ln_kernel(const float* __restrict__ in,
                          const float* __restrict__ gw,
                          const float* __restrict__ gb,
                          __half* __restrict__ out) {
    int r   = blockIdx.x;
    int tid = threadIdx.x;
    int src = REMAP ? remap_row(r) : r;
    const float* px = in + (size_t)src * C_DIM;

    float v[3];
    float sum = 0.f, sq = 0.f;
#pragma unroll
    for (int i = 0; i < 3; ++i) {
        float t = px[tid + i * 128];
        v[i] = t; sum += t; sq += t * t;
    }
#pragma unroll
    for (int o = 16; o > 0; o >>= 1) {
        sum += __shfl_xor_sync(0xffffffffu, sum, o);
        sq  += __shfl_xor_sync(0xffffffffu, sq,  o);
    }
    __shared__ float red[8];
    int warp = tid >> 5;
    if ((tid & 31) == 0) { red[warp] = sum; red[4 + warp] = sq; }
    __syncthreads();
    float ts = red[0] + red[1] + red[2] + red[3];
    float tq = red[4] + red[5] + red[6] + red[7];
    float mean = ts * (1.0f / C_DIM);
    float var  = tq * (1.0f / C_DIM) - mean * mean;
    float rstd = rsqrtf(var + 1e-5f);

    __half* po = out + (size_t)r * C_DIM;
#pragma unroll
    for (int i = 0; i < 3; ++i) {
        int c = tid + i * 128;
        po[c] = __float2half((v[i] - mean) * rstd * gw[c] + gb[c]);
    }
}

// ---------------------------------------------------------------------------
// FP16 tensor-core GEMM, 3-stage cp.async pipeline (unchanged from R4).
// ---------------------------------------------------------------------------
#define BM 128
#define BN 128
#define BK 32
#define LDH 40
#define STAGE_H (128 * LDH)

template<int EPI, typename OutT>
__global__ __launch_bounds__(256, 2)
void gemm_h(const __half* __restrict__ A, const __half* __restrict__ B,
            const float* __restrict__ bias, OutT* __restrict__ Cmat,
            int M, int N, int K, const float* __restrict__ res) {
    extern __shared__ __half smh[];
    __half* smA = smh;
    __half* smB = smh + 3 * STAGE_H;
    float*  smC = (float*)smh;

    const int tid  = threadIdx.x;
    const int warp = tid >> 5;
    const int lane = tid & 31;
    const int wm = warp >> 1;
    const int wn = warp & 1;
    const int m0 = blockIdx.y * BM, n0 = blockIdx.x * BN;

    wmma::fragment<wmma::accumulator, 16, 16, 16, float> acc[2][4];
#pragma unroll
    for (int i = 0; i < 2; ++i)
#pragma unroll
        for (int j = 0; j < 4; ++j) wmma::fill_fragment(acc[i][j], 0.0f);

    auto load_stage = [&](int stage, int k0) {
        __half* as = smA + stage * STAGE_H;
        __half* bs = smB + stage * STAGE_H;
#pragma unroll
        for (int l = 0; l < 2; ++l) {
            int f   = tid + l * 256;
            int row = f >> 2;
            int col = (f & 3) * 8;
            cp16(&as[row * LDH + col], &A[(size_t)(m0 + row) * K + k0 + col]);
            cp16(&bs[row * LDH + col], &B[(size_t)(n0 + row) * K + k0 + col]);
        }
        CP_COMMIT();
    };

    const int nt = K / BK;
    load_stage(0, 0);
    load_stage(1, BK);

    for (int t = 0; t < nt; ++t) {
        if (t + 1 < nt) { CP_WAIT1(); } else { CP_WAIT0(); }
        __syncthreads();

        const __half* as = smA + (t % 3) * STAGE_H;
        const __half* bs = smB + (t % 3) * STAGE_H;
#pragma unroll
        for (int kk = 0; kk < BK; kk += 16) {
            wmma::fragment<wmma::matrix_a, 16, 16, 16, __half, wmma::row_major> fa[2];
            wmma::fragment<wmma::matrix_b, 16, 16, 16, __half, wmma::col_major> fb[4];
#pragma unroll
            for (int i = 0; i < 2; ++i)
                wmma::load_matrix_sync(fa[i], &as[(wm * 32 + i * 16) * LDH + kk], LDH);
#pragma unroll
            for (int j = 0; j < 4; ++j)
                wmma::load_matrix_sync(fb[j], &bs[(wn * 64 + j * 16) * LDH + kk], LDH);
#pragma unroll
            for (int i = 0; i < 2; ++i)
#pragma unroll
                for (int j = 0; j < 4; ++j)
                    wmma::mma_sync(acc[i][j], fa[i], fb[j], acc[i][j]);
        }
        if (t + 2 < nt) load_stage((t + 2) % 3, (t + 2) * BK);
        __syncthreads();
    }

    float* cw = smC + warp * 16 * 20;
#pragma unroll
    for (int i = 0; i < 2; ++i) {
#pragma unroll
        for (int j = 0; j < 4; ++j) {
            wmma::store_matrix_sync(cw, acc[i][j], 20, wmma::mem_row_major);
            __syncwarp();
            int rbase = m0 + wm * 32 + i * 16;
            int cbase = n0 + wn * 64 + j * 16;
#pragma unroll
            for (int t = 0; t < 8; ++t) {
                int e  = t * 32 + lane;
                int rr = e >> 4, cc = e & 15;
                float v = cw[rr * 20 + cc];
                int r = rbase + rr, c = cbase + cc;
                v += bias[c];
                if (EPI == 1) v = 0.5f * v * (1.0f + erff(v * 0.70710678118654752f));
                size_t rowoff = (EPI == 3) ? (size_t)remap_row(r) * N : (size_t)r * N;
                if (EPI == 2 || EPI == 3) v += res[rowoff + c];
                Cmat[rowoff + c] = (OutT)v;
            }
            __syncwarp();
        }
    }
}
#define GEMM_SMEM (6 * STAGE_H * (int)sizeof(__half))

// ---------------------------------------------------------------------------
// Tensor-core attention: block per (window, head), 256 threads (8 warps).
// Q/K/V padded to 112 rows in smem (half, ld 40).
// Scores: 49 wmma 16x16x(k=32) tiles -> staged fp32 -> scale+bias+mask -> half.
// Softmax fp32 per row. P@V: 14 wmma tiles -> half out.
// ---------------------------------------------------------------------------
#define ALD 40
#define SLD 120
#define ATT_SMEM ((3 * 112 * ALD + 112 * SLD) * 2 + 8 * 320 * 4)   // 64000 B

__global__ __launch_bounds__(256)
void attn_wmma(const __half* __restrict__ qkv,
               const float* __restrict__ rpb,
               __half* __restrict__ out) {
    extern __shared__ __half smh[];
    __half* qs = smh;                      // [112][40]
    __half* ks = qs + 112 * ALD;
    __half* vs = ks + 112 * ALD;
    __half* sc = vs + 112 * ALD;           // [112][120]
    float*  stg = (float*)(sc + 112 * SLD); // 8 warps x 16x20

    const int b_   = blockIdx.x;
    const int head = blockIdx.y;
    const int tid  = threadIdx.x;
    const int warp = tid >> 5;
    const int lane = tid & 31;
    const float scale = 0.17677669529663687f;

    // load Q,K,V (uint4 = 8 halves); pad rows 98..111 with zero
    for (int idx = tid; idx < 112 * 4; idx += 256) {
        int row = idx >> 2, seg = idx & 3;
        uint4 vq = make_uint4(0,0,0,0), vk = vq, vv = vq;
        if (row < NWIN) {
            const __half* p = qkv + ((size_t)(b_ * NWIN + row)) * (3 * C_DIM) + head * HD;
            vq = ((const uint4*)p)[seg];
            vk = ((const uint4*)(p + C_DIM))[seg];
            vv = ((const uint4*)(p + 2 * C_DIM))[seg];
        }
        *(uint4*)&qs[row * ALD + seg * 8] = vq;
        *(uint4*)&ks[row * ALD + seg * 8] = vk;
        *(uint4*)&vs[row * ALD + seg * 8] = vv;
    }
    __syncthreads();

    const int widx = b_ & 255;
    const int dI = widx >> 6, hI = (widx >> 3) & 7, wI = widx & 7;
    float* mystg = stg + warp * 320;

    // ---- scores ----
    for (int tt = warp; tt < 49; tt += 8) {
        int ti = tt / 7, tj = tt - ti * 7;
        wmma::fragment<wmma::accumulator, 16, 16, 16, float> c;
        wmma::fill_fragment(c, 0.0f);
#pragma unroll
        for (int kk = 0; kk < HD; kk += 16) {
            wmma::fragment<wmma::matrix_a, 16, 16, 16, __half, wmma::row_major> fa;
            wmma::fragment<wmma::matrix_b, 16, 16, 16, __half, wmma::col_major> fb;
            wmma::load_matrix_sync(fa, &qs[(ti * 16) * ALD + kk], ALD);
            wmma::load_matrix_sync(fb, &ks[(tj * 16) * ALD + kk], ALD);
            wmma::mma_sync(c, fa, fb, c);
        }
        wmma::store_matrix_sync(mystg, c, 20, wmma::mem_row_major);
        __syncwarp();
#pragma unroll
        for (int t = 0; t < 8; ++t) {
            int e = t * 32 + lane;
            int rr = e >> 4, cc = e & 15;
            int n = ti * 16 + rr, m = tj * 16 + cc;
            float s = 0.f;
            if (n < NWIN && m < NWIN) {
                s = mystg[rr * 20 + cc] * scale;
                int nd = n / 49, nr = n - nd * 49, nh = nr / 7, nw = nr - nh * 7;
                int md = m / 49, mr = m - md * 49, mh = mr / 7, mw = mr - mh * 7;
                int ridx = (nd - md + 1) * 169 + (nh - mh + 6) * 13 + (nw - mw + 6);
                s += rpb[ridx * HEADS + head];
                int gdn = dI * 2 + nd, ghn = hI * 7 + nh, gwn = wI * 7 + nw;
                int gdm = dI * 2 + md, ghm = hI * 7 + mh, gwm = wI * 7 + mw;
                int ln = (gdn < 6 ? 0 : (gdn < 7 ? 1 : 2)) * 9
                       + (ghn < 49 ? 0 : (ghn < 53 ? 1 : 2)) * 3
                       + (gwn < 49 ? 0 : (gwn < 53 ? 1 : 2));
                int lm = (gdm < 6 ? 0 : (gdm < 7 ? 1 : 2)) * 9
                       + (ghm < 49 ? 0 : (ghm < 53 ? 1 : 2)) * 3
                       + (gwm < 49 ? 0 : (gwm < 53 ? 1 : 2));
                if (ln != lm) s -= 100.0f;
            }
            sc[n * SLD + m] = __float2half(s);
        }
        __syncwarp();
    }
    __syncthreads();

    // ---- softmax (fp32 math, half storage) ----
    if (tid < NWIN) {
        __half* row = sc + tid * SLD;
        float mx = -1e30f;
        for (int m = 0; m < NWIN; ++m) mx = fmaxf(mx, __half2float(row[m]));
        float sum = 0.f;
        for (int m = 0; m < NWIN; ++m) {
            float e = __expf(__half2float(row[m]) - mx);
            sum += e;
            row[m] = __float2half(e);
        }
        float inv = 1.0f / sum;
        for (int m = 0; m < NWIN; ++m)
            row[m] = __float2half(__half2float(row[m]) * inv);
        for (int m = NWIN; m < 112; ++m) row[m] = __float2half(0.f);
    } else if (tid >= 128 && tid - 128 < 14) {
        // zero padded rows 98..111 (they feed garbage-free A tiles)
        __half* row = sc + (NWIN + tid - 128) * SLD;
        for (int m = 0; m < 112; ++m) row[m] = __float2half(0.f);
    }
    __syncthreads();

    // ---- P @ V ----
    for (int tt = warp; tt < 14; tt += 8) {
        int ti = tt >> 1, tj = tt & 1;
        wmma::fragment<wmma::accumulator, 16, 16, 16, float> c;
        wmma::fill_fragment(c, 0.0f);
#pragma unroll
        for (int kt = 0; kt < 7; ++kt) {
            wmma::fragment<wmma::matrix_a, 16, 16, 16, __half, wmma::row_major> fa;
            wmma::fragment<wmma::matrix_b, 16, 16, 16, __half, wmma::row_major> fb;
            wmma::load_matrix_sync(fa, &sc[(ti * 16) * SLD + kt * 16], SLD);
            wmma::load_matrix_sync(fb, &vs[(kt * 16) * ALD + tj * 16], ALD);
            wmma::mma_sync(c, fa, fb, c);
        }
        wmma::store_matrix_sync(mystg, c, 20, wmma::mem_row_major);
        __syncwarp();
#pragma unroll
        for (int t = 0; t < 8; ++t) {
            int e = t * 32 + lane;
            int rr = e >> 4, cc = e & 15;
            int n = ti * 16 + rr;
            if (n < NWIN)
                out[((size_t)(b_ * NWIN + n)) * C_DIM + head * HD + tj * 16 + cc] =
                    __float2half(mystg[rr * 20 + cc]);
        }
        __syncwarp();
    }
}

// ---------------------------------------------------------------------------
extern "C" void kernel_launch(void* const* d_in, const int* in_sizes, int n_in,
                              void* d_out, int out_size) {
    const float* x     = (const float*)d_in[0];
    const float* n1w   = (const float*)d_in[1];
    const float* n1b   = (const float*)d_in[2];
    const float* qkvw  = (const float*)d_in[3];
    const float* qkvb  = (const float*)d_in[4];
    const float* rpb   = (const float*)d_in[5];
    const float* projw = (const float*)d_in[6];
    const float* projb = (const float*)d_in[7];
    const float* n2w   = (const float*)d_in[8];
    const float* n2b   = (const float*)d_in[9];
    const float* fc1w  = (const float*)d_in[10];
    const float* fc1b  = (const float*)d_in[11];
    const float* fc2w  = (const float*)d_in[12];
    const float* fc2b  = (const float*)d_in[13];
    float* out = (float*)d_out;

    __half *xw, *qkv, *att, *ln2, *fc1, *qkvwh, *projwh, *fc1wh, *fc2wh;
    float *x1;
    cudaGetSymbolAddress((void**)&xw,    g_xw);
    cudaGetSymbolAddress((void**)&qkv,   g_qkv);
    cudaGetSymbolAddress((void**)&att,   g_att);
    cudaGetSymbolAddress((void**)&x1,    g_x1);
    cudaGetSymbolAddress((void**)&ln2,   g_ln2);
    cudaGetSymbolAddress((void**)&fc1,   g_fc1);
    cudaGetSymbolAddress((void**)&qkvwh, g_qkvw);
    cudaGetSymbolAddress((void**)&projwh,g_projw);
    cudaGetSymbolAddress((void**)&fc1wh, g_fc1w);
    cudaGetSymbolAddress((void**)&fc2wh, g_fc2w);

    cudaFuncSetAttribute(attn_wmma, cudaFuncAttributeMaxDynamicSharedMemorySize, ATT_SMEM);
    cudaFuncSetAttribute(gemm_h<0,__half>, cudaFuncAttributeMaxDynamicSharedMemorySize, GEMM_SMEM);
    cudaFuncSetAttribute(gemm_h<1,__half>, cudaFuncAttributeMaxDynamicSharedMemorySize, GEMM_SMEM);
    cudaFuncSetAttribute(gemm_h<2,float>,  cudaFuncAttributeMaxDynamicSharedMemorySize, GEMM_SMEM);
    cudaFuncSetAttribute(gemm_h<3,float>,  cudaFuncAttributeMaxDynamicSharedMemorySize, GEMM_SMEM);

    // 0. weight conversions
    cvt_kernel<<<(3*C_DIM*C_DIM + 255)/256, 256>>>(qkvw, qkvwh, 3*C_DIM*C_DIM);
    cvt_kernel<<<(C_DIM*C_DIM   + 255)/256, 256>>>(projw, projwh, C_DIM*C_DIM);
    cvt_kernel<<<(HID*C_DIM     + 255)/256, 256>>>(fc1w, fc1wh, HID*C_DIM);
    cvt_kernel<<<(C_DIM*HID     + 255)/256, 256>>>(fc2w, fc2wh, C_DIM*HID);

    // 1. LN1 + shift + window partition (half)
    ln_kernel<true><<<T_TOK, 128>>>(x, n1w, n1b, xw);

    // 2. QKV projection (half out)
    gemm_h<0,__half><<<dim3(1152/128, T_TOK/128), 256, GEMM_SMEM>>>(
        xw, qkvwh, qkvb, qkv, T_TOK, 3*C_DIM, C_DIM, nullptr);

    // 3. Windowed attention (tensor cores)
    attn_wmma<<<dim3(BWIN, HEADS), 256, ATT_SMEM>>>(qkv, rpb, att);

    // 4. Proj + reverse + shortcut (fp32 out)
    gemm_h<3,float><<<dim3(C_DIM/128, T_TOK/128), 256, GEMM_SMEM>>>(
        att, projwh, projb, x1, T_TOK, C_DIM, C_DIM, x);

    // 5. LN2 (half)
    ln_kernel<false><<<T_TOK, 128>>>(x1, n2w, n2b, ln2);

    // 6. FC1 + GELU (half)
    gemm_h<1,__half><<<dim3(HID/128, T_TOK/128), 256, GEMM_SMEM>>>(
        ln2, fc1wh, fc1b, fc1, T_TOK, HID, C_DIM, nullptr);

    // 7. FC2 + residual (fp32 -> d_out)
    gemm_h<2,float><<<dim3(C_DIM/128, T_TOK/128), 256, GEMM_SMEM>>>(
        fc1, fc2wh, fc2b, out, T_TOK, C_DIM, HID, x1);
}